// round 2
// baseline (speedup 1.0000x reference)
#include <cuda_runtime.h>
#include <math.h>

#define BSZ   1024
#define NBIN  4
#define BSIN  128
#define NKEY  5
#define NBO   8
#define BSO   512
#define NHID  4096
#define DKQ   64
#define GATES 2048

// ------------- scratch (allocation-free: __device__ globals) -------------
__device__ float g_inp_use[(size_t)BSZ * NBO * BSO];
__device__ float g_gates  [(size_t)BSZ * NBO * GATES];
__device__ float g_hnew   [(size_t)BSZ * NBO * BSO];
__device__ float g_q2     [(size_t)BSZ * NBO * DKQ];
__device__ float g_k2     [(size_t)BSZ * NBO * DKQ];
__device__ float g_v2     [(size_t)BSZ * NBO * DKQ];
__device__ float g_mblk   [(size_t)BSZ * NBO];

__device__ __forceinline__ float sigf(float x) { return 1.0f / (1.0f + expf(-x)); }

// ------------- f32x2 packed FMA helpers (sm_103a) -------------
__device__ __forceinline__ unsigned long long pk2(float x, float y) {
    unsigned long long r;
    asm("mov.b64 %0, {%1, %2};" : "=l"(r) : "f"(x), "f"(y));
    return r;
}
__device__ __forceinline__ void fma2(unsigned long long& d, unsigned long long a, unsigned long long b) {
    asm("fma.rn.f32x2 %0, %1, %2, %0;" : "+l"(d) : "l"(a), "l"(b));
}
__device__ __forceinline__ float2 upk2(unsigned long long v) {
    float2 f;
    asm("mov.b64 {%0, %1}, %2;" : "=f"(f.x), "=f"(f.y) : "l"(v));
    return f;
}

// =====================================================================
// K1: input attention + top-4 mask.  4 batch elements per CTA.
// =====================================================================
#define K1_BPB 4
__global__ void __launch_bounds__(256) k1_input_attn(
    const float* __restrict__ inp, const float* __restrict__ hx,
    const float* __restrict__ wq, const float* __restrict__ wk, const float* __restrict__ wv,
    const float* __restrict__ fcw, const float* __restrict__ fcb,
    float* __restrict__ mask_out)
{
    __shared__ float sx[K1_BPB][NKEY * BSIN];
    __shared__ float sk[K1_BPB][NKEY][DKQ];
    __shared__ float sv[K1_BPB][NKEY][DKQ];
    __shared__ float sq[K1_BPB][NBO][DKQ];
    __shared__ float so[K1_BPB][NBO][DKQ];
    __shared__ float sattn[K1_BPB][NBO][NKEY];
    __shared__ float smb[K1_BPB][NBO];

    const int tid = threadIdx.x;
    const int b0  = blockIdx.x * K1_BPB;

    // x with appended zero block
    for (int i = tid; i < K1_BPB * NKEY * BSIN; i += 256) {
        int bi = i / (NKEY * BSIN);
        int j  = i % (NKEY * BSIN);
        sx[bi][j] = (j < NBIN * BSIN) ? inp[(size_t)(b0 + bi) * (NBIN * BSIN) + j] : 0.0f;
    }
    __syncthreads();

    // k, v
    for (int g = tid; g < K1_BPB * NKEY * (DKQ / 4); g += 256) {
        int bi = g / (NKEY * 16);
        int r  = g % (NKEY * 16);
        int n  = r / 16;
        int e4 = (r % 16) * 4;
        const float* xp  = &sx[bi][n * BSIN];
        const float* wkp = wk + (size_t)(n * BSIN) * DKQ + e4;
        const float* wvp = wv + (size_t)(n * BSIN) * DKQ + e4;
        float4 ak = make_float4(0.f, 0.f, 0.f, 0.f);
        float4 av = make_float4(0.f, 0.f, 0.f, 0.f);
        for (int d = 0; d < BSIN; d++) {
            float xv  = xp[d];
            float4 a4 = *(const float4*)(wkp + (size_t)d * DKQ);
            float4 b4 = *(const float4*)(wvp + (size_t)d * DKQ);
            ak.x += xv * a4.x; ak.y += xv * a4.y; ak.z += xv * a4.z; ak.w += xv * a4.w;
            av.x += xv * b4.x; av.y += xv * b4.y; av.z += xv * b4.z; av.w += xv * b4.w;
        }
        *(float4*)&sk[bi][n][e4] = ak;
        *(float4*)&sv[bi][n][e4] = av;
    }

    // q
    for (int g = tid; g < K1_BPB * NBO * (DKQ / 4); g += 256) {
        int bi = g / (NBO * 16);
        int r  = g % (NBO * 16);
        int n  = r / 16;
        int e4 = (r % 16) * 4;
        const float* hp = hx + (size_t)(b0 + bi) * NHID + n * BSO;
        const float* wp = wq + (size_t)(n * BSO) * DKQ + e4;
        float4 a = make_float4(0.f, 0.f, 0.f, 0.f);
        for (int d = 0; d < BSO; d++) {
            float hv  = __ldg(hp + d);
            float4 w4 = *(const float4*)(wp + (size_t)d * DKQ);
            a.x += hv * w4.x; a.y += hv * w4.y; a.z += hv * w4.z; a.w += hv * w4.w;
        }
        *(float4*)&sq[bi][n][e4] = a;
    }
    __syncthreads();

    // scores + softmax (32 rows)
    if (tid < K1_BPB * NBO) {
        int bi = tid / NBO, n = tid % NBO;
        float s[NKEY];
        float mx = -1e30f;
        for (int j = 0; j < NKEY; j++) {
            float a = 0.f;
            for (int e = 0; e < DKQ; e++) a += sq[bi][n][e] * sk[bi][j][e];
            a *= 0.125f;
            s[j] = a;
            mx = fmaxf(mx, a);
        }
        float den = 0.f;
        for (int j = 0; j < NKEY; j++) { s[j] = expf(s[j] - mx); den += s[j]; }
        float inv = 1.0f / den;
        for (int j = 0; j < NKEY; j++) sattn[bi][n][j] = s[j] * inv;
    }
    __syncthreads();

    // top-4 mask
    if (tid < K1_BPB) {
        int bi = tid;
        float sc[NBO], t[NBO];
        for (int n = 0; n < NBO; n++) { sc[n] = sattn[bi][n][0]; t[n] = sc[n]; }
        for (int a = 0; a < 4; a++) {
            int mi = a;
            for (int b = a + 1; b < NBO; b++) if (t[b] > t[mi]) mi = b;
            float tmp = t[a]; t[a] = t[mi]; t[mi] = tmp;
        }
        float thr = t[3] - 0.01f;
        for (int n = 0; n < NBO; n++) {
            float m = (sc[n] > thr) ? 1.0f : 0.0f;
            smb[bi][n] = m;
            g_mblk[(size_t)(b0 + bi) * NBO + n] = m;
        }
    }
    __syncthreads();

    // o = attn @ v
    for (int i = tid; i < K1_BPB * NBO * DKQ; i += 256) {
        int bi = i / (NBO * DKQ);
        int r  = i % (NBO * DKQ);
        int n  = r / DKQ;
        int e  = r % DKQ;
        float a = 0.f;
        for (int j = 0; j < NKEY; j++) a += sattn[bi][n][j] * sv[bi][j][e];
        so[bi][n][e] = a;
    }
    __syncthreads();

    // inp_use = o @ fcw + fcb; write mask
    for (int g = tid; g < K1_BPB * NBO * (BSO / 4); g += 256) {
        int bi = g / (NBO * 128);
        int r  = g % (NBO * 128);
        int n  = r / 128;
        int c4 = (r % 128) * 4;
        float4 a = *(const float4*)&fcb[c4];
        const float* sp = so[bi][n];
        for (int e = 0; e < DKQ; e++) {
            float s   = sp[e];
            float4 w4 = *(const float4*)&fcw[(size_t)e * BSO + c4];
            a.x += s * w4.x; a.y += s * w4.y; a.z += s * w4.z; a.w += s * w4.w;
        }
        *(float4*)&g_inp_use[((size_t)(b0 + bi) * NBO + n) * BSO + c4] = a;
        float m = smb[bi][n];
        *(float4*)&mask_out[(size_t)(b0 + bi) * NHID + n * BSO + c4] = make_float4(m, m, m, m);
    }
}

// =====================================================================
// K2: LSTM gate GEMM (dominant).  Per kb: M=1024, N=2048, K=2x512.
//   Tile 128x128, kc=16, 256 threads, 8x8 microtile, FFMA2.
// =====================================================================
__device__ __forceinline__ void k2_load(
    int ch, int tid, int mb, int kb, int nb,
    const float* __restrict__ hx,
    const float* __restrict__ w_ih, const float* __restrict__ w_hh,
    float4* pa, float4* pb)
{
    const int phase = ch >> 5;
    const int kc    = (ch & 31) * 16;
#pragma unroll
    for (int p = 0; p < 2; p++) {
        int idx = p * 256 + tid;
        int m   = idx >> 2;
        int k4  = (idx & 3) << 2;
        const float* src = (phase == 0)
            ? &g_inp_use[((size_t)(mb + m) * NBO + kb) * BSO + kc + k4]
            : &hx[(size_t)(mb + m) * NHID + kb * BSO + kc + k4];
        pa[p] = *(const float4*)src;
    }
    const float* wsrc = ((phase == 0) ? w_ih : w_hh) + (size_t)kb * BSO * GATES;
#pragma unroll
    for (int p = 0; p < 2; p++) {
        int idx = p * 256 + tid;
        int kk  = idx >> 5;
        int nq  = (idx & 31) << 2;
        pb[p] = *(const float4*)&wsrc[(size_t)(kc + kk) * GATES + nb + nq];
    }
}

__global__ void __launch_bounds__(256) k2_lstm_gemm(
    const float* __restrict__ hx,
    const float* __restrict__ w_ih, const float* __restrict__ w_hh,
    const float* __restrict__ b_ih, const float* __restrict__ b_hh)
{
    __shared__ float As[128][20];
    __shared__ float Bs[16][128];

    const int tid = threadIdx.x;
    const int nb  = blockIdx.x * 128;
    const int mb  = blockIdx.y * 128;
    const int kb  = blockIdx.z;
    const int tx  = tid & 15;
    const int ty  = tid >> 4;

    unsigned long long acc[8][4];
#pragma unroll
    for (int mi = 0; mi < 8; mi++)
#pragma unroll
        for (int np = 0; np < 4; np++) acc[mi][np] = 0ULL;

    float4 pa[2], pb[2];
    k2_load(0, tid, mb, kb, nb, hx, w_ih, w_hh, pa, pb);

    for (int ch = 0; ch < 64; ch++) {
        // store prefetched tile to smem
#pragma unroll
        for (int p = 0; p < 2; p++) {
            int idx = p * 256 + tid;
            int m   = idx >> 2;
            int k4  = (idx & 3) << 2;
            *(float4*)&As[m][k4] = pa[p];
        }
#pragma unroll
        for (int p = 0; p < 2; p++) {
            int idx = p * 256 + tid;
            int kk  = idx >> 5;
            int nq  = (idx & 31) << 2;
            *(float4*)&Bs[kk][nq] = pb[p];
        }
        __syncthreads();

        if (ch < 63) k2_load(ch + 1, tid, mb, kb, nb, hx, w_ih, w_hh, pa, pb);

#pragma unroll
        for (int kg = 0; kg < 4; kg++) {
            float4 af[8];
#pragma unroll
            for (int mi = 0; mi < 8; mi++)
                af[mi] = *(const float4*)&As[ty + 16 * mi][kg * 4];
#pragma unroll
            for (int k = 0; k < 4; k++) {
                float4 bA = *(const float4*)&Bs[kg * 4 + k][tx * 4];
                float4 bB = *(const float4*)&Bs[kg * 4 + k][tx * 4 + 64];
                unsigned long long b0 = pk2(bA.x, bA.y);
                unsigned long long b1 = pk2(bA.z, bA.w);
                unsigned long long b2 = pk2(bB.x, bB.y);
                unsigned long long b3 = pk2(bB.z, bB.w);
#pragma unroll
                for (int mi = 0; mi < 8; mi++) {
                    float a = (k == 0) ? af[mi].x : (k == 1) ? af[mi].y
                            : (k == 2) ? af[mi].z : af[mi].w;
                    unsigned long long aa = pk2(a, a);
                    fma2(acc[mi][0], aa, b0);
                    fma2(acc[mi][1], aa, b1);
                    fma2(acc[mi][2], aa, b2);
                    fma2(acc[mi][3], aa, b3);
                }
            }
        }
        __syncthreads();
    }

    float4 x0 = *(const float4*)&b_ih[(size_t)kb * GATES + nb + tx * 4];
    float4 y0 = *(const float4*)&b_hh[(size_t)kb * GATES + nb + tx * 4];
    float4 x1 = *(const float4*)&b_ih[(size_t)kb * GATES + nb + 64 + tx * 4];
    float4 y1 = *(const float4*)&b_hh[(size_t)kb * GATES + nb + 64 + tx * 4];
    float4 bia0 = make_float4(x0.x + y0.x, x0.y + y0.y, x0.z + y0.z, x0.w + y0.w);
    float4 bia1 = make_float4(x1.x + y1.x, x1.y + y1.y, x1.z + y1.z, x1.w + y1.w);

#pragma unroll
    for (int mi = 0; mi < 8; mi++) {
        int m = mb + ty + 16 * mi;
        float2 c0 = upk2(acc[mi][0]);
        float2 c1 = upk2(acc[mi][1]);
        float2 c2 = upk2(acc[mi][2]);
        float2 c3 = upk2(acc[mi][3]);
        float4 r0 = make_float4(c0.x + bia0.x, c0.y + bia0.y, c1.x + bia0.z, c1.y + bia0.w);
        float4 r1 = make_float4(c2.x + bia1.x, c2.y + bia1.y, c3.x + bia1.z, c3.y + bia1.w);
        size_t base = ((size_t)m * NBO + kb) * GATES + nb;
        *(float4*)&g_gates[base + tx * 4]      = r0;
        *(float4*)&g_gates[base + 64 + tx * 4] = r1;
    }
}

// =====================================================================
// K3: LSTM elementwise; writes h_new and cx_out (mask applied).
// =====================================================================
__global__ void __launch_bounds__(256) k3_lstm_ew(
    const float* __restrict__ cx, float* __restrict__ cx_out)
{
    size_t i = (size_t)blockIdx.x * blockDim.x + threadIdx.x;
    if (i >= (size_t)BSZ * NBO * BSO) return;
    size_t bk = i / BSO;
    int d = (int)(i % BSO);
    const float* g = &g_gates[bk * GATES];
    float ig = sigf(g[d]);
    float fg = sigf(g[d + 512]);
    float gg = tanhf(g[d + 1024]);
    float og = sigf(g[d + 1536]);
    float cb = cx[bk * BSO + d];
    float cn = fg * cb + ig * gg;
    float hn = og * tanhf(cn);
    g_hnew[i] = hn;
    float m = g_mblk[bk];
    cx_out[bk * BSO + d] = m * cn + (1.0f - m) * cb;
}

// =====================================================================
// K4: q2/k2/v2 = h_new @ mha_w{q,k,v}.  Per (kb, mtile of 64): M=64,N=192,K=512.
// =====================================================================
__global__ void __launch_bounds__(256) k4_qkv(
    const float* __restrict__ wq, const float* __restrict__ wk, const float* __restrict__ wv)
{
    __shared__ float hs[64][33];
    __shared__ float ws[32][196];

    const int tid = threadIdx.x;
    const int kb  = blockIdx.x;
    const int mb  = blockIdx.y * 64;
    const int ty  = tid >> 4;    // 0..15 -> 4 rows each
    const int tx  = tid & 15;    // 0..15 -> 12 cols each

    float acc[4][12];
#pragma unroll
    for (int j = 0; j < 4; j++)
#pragma unroll
        for (int c = 0; c < 12; c++) acc[j][c] = 0.f;

    for (int kc = 0; kc < BSO; kc += 32) {
        for (int i = tid; i < 64 * 32; i += 256) {
            int r  = i >> 5;
            int kk = i & 31;
            hs[r][kk] = g_hnew[((size_t)(mb + r) * NBO + kb) * BSO + kc + kk];
        }
        for (int i = tid; i < 32 * 192; i += 256) {
            int kk = i / 192;
            int c  = i % 192;
            int m  = c >> 6;
            int n  = c & 63;
            const float* w = (m == 0) ? wq : (m == 1) ? wk : wv;
            ws[kk][c] = w[(size_t)kb * BSO * DKQ + (size_t)(kc + kk) * DKQ + n];
        }
        __syncthreads();

#pragma unroll 4
        for (int kk = 0; kk < 32; kk++) {
            float a[4], b[12];
#pragma unroll
            for (int j = 0; j < 4; j++) a[j] = hs[ty * 4 + j][kk];
#pragma unroll
            for (int c = 0; c < 12; c++) b[c] = ws[kk][tx * 12 + c];
#pragma unroll
            for (int j = 0; j < 4; j++)
#pragma unroll
                for (int c = 0; c < 12; c++) acc[j][c] += a[j] * b[c];
        }
        __syncthreads();
    }

#pragma unroll
    for (int j = 0; j < 4; j++) {
        int b = mb + ty * 4 + j;
#pragma unroll
        for (int c = 0; c < 12; c++) {
            int col = tx * 12 + c;
            int m   = col >> 6;
            int n   = col & 63;
            float* dst = (m == 0) ? g_q2 : (m == 1) ? g_k2 : g_v2;
            dst[((size_t)b * NBO + kb) * DKQ + n] = acc[j][c];
        }
    }
}

// =====================================================================
// K5: MHA attend + fc/gate + final hx_out.  One CTA per batch element.
// =====================================================================
__global__ void __launch_bounds__(256) k5_mha(
    const float* __restrict__ hx,
    const float* __restrict__ fcw, const float* __restrict__ fcb,
    const float* __restrict__ gw,  const float* __restrict__ gb,
    float* __restrict__ hx_out)
{
    __shared__ float sq2[NBO][DKQ];
    __shared__ float sk2[NBO][DKQ];
    __shared__ float sv2[NBO][DKQ];
    __shared__ float sat[NBO][NBO];
    __shared__ float so2[NBO][DKQ];

    const int tid = threadIdx.x;
    const size_t b = blockIdx.x;

    for (int i = tid; i < NBO * DKQ; i += 256) {
        ((float*)sq2)[i] = g_q2[b * NBO * DKQ + i];
        ((float*)sk2)[i] = g_k2[b * NBO * DKQ + i];
        ((float*)sv2)[i] = g_v2[b * NBO * DKQ + i];
    }
    __syncthreads();

    if (tid < 64) {
        int kq = tid >> 3, kj = tid & 7;
        float s = 0.f;
        for (int e = 0; e < DKQ; e++) s += sq2[kq][e] * sk2[kj][e];
        sat[kq][kj] = s * 0.125f;
    }
    __syncthreads();
    if (tid < NBO) {
        float mx = -1e30f;
        for (int j = 0; j < NBO; j++) mx = fmaxf(mx, sat[tid][j]);
        float den = 0.f;
        for (int j = 0; j < NBO; j++) { float e = expf(sat[tid][j] - mx); sat[tid][j] = e; den += e; }
        float inv = 1.0f / den;
        for (int j = 0; j < NBO; j++) sat[tid][j] *= inv;
    }
    __syncthreads();
    for (int i = tid; i < NBO * DKQ; i += 256) {
        int k = i >> 6, e = i & 63;
        float a = 0.f;
        for (int j = 0; j < NBO; j++) a += sat[k][j] * sv2[j][e];
        so2[k][e] = a;
    }
    __syncthreads();

    // out/gate: thread owns 2 consecutive d for ALL 8 blocks (weight reuse x8)
    const int d0 = tid * 2;
    float2 ao[NBO], ag[NBO];
#pragma unroll
    for (int k = 0; k < NBO; k++) { ao[k] = make_float2(0.f, 0.f); ag[k] = make_float2(0.f, 0.f); }

    for (int e = 0; e < DKQ; e++) {
        float2 fw = *(const float2*)&fcw[(size_t)e * BSO + d0];
        float2 gwv = *(const float2*)&gw[(size_t)e * BSO + d0];
#pragma unroll
        for (int k = 0; k < NBO; k++) {
            float o = so2[k][e];
            ao[k].x += o * fw.x;  ao[k].y += o * fw.y;
            ag[k].x += o * gwv.x; ag[k].y += o * gwv.y;
        }
    }

    float fb0 = fcb[d0], fb1 = fcb[d0 + 1];
    float gb0 = gb[d0],  gb1 = gb[d0 + 1];
#pragma unroll
    for (int k = 0; k < NBO; k++) {
        float m = g_mblk[b * NBO + k];
        float hn0 = g_hnew[(b * NBO + k) * BSO + d0];
        float hn1 = g_hnew[(b * NBO + k) * BSO + d0 + 1];
        float v0 = hn0 + sigf(ag[k].x + gb0) * tanhf(ao[k].x + fb0);
        float v1 = hn1 + sigf(ag[k].y + gb1) * tanhf(ao[k].y + fb1);
        size_t idx = b * NHID + (size_t)k * BSO + d0;
        hx_out[idx]     = m * v0 + (1.0f - m) * hx[idx];
        hx_out[idx + 1] = m * v1 + (1.0f - m) * hx[idx + 1];
    }
}

// =====================================================================
extern "C" void kernel_launch(void* const* d_in, const int* in_sizes, int n_in,
                              void* d_out, int out_size) {
    const float* inp    = (const float*)d_in[0];
    const float* hx     = (const float*)d_in[1];
    const float* cx     = (const float*)d_in[2];
    const float* ia_wq  = (const float*)d_in[3];
    const float* ia_wk  = (const float*)d_in[4];
    const float* ia_wv  = (const float*)d_in[5];
    const float* ia_fcw = (const float*)d_in[6];
    const float* ia_fcb = (const float*)d_in[7];
    const float* mha_wq = (const float*)d_in[8];
    const float* mha_wk = (const float*)d_in[9];
    const float* mha_wv = (const float*)d_in[10];
    const float* mha_fcw= (const float*)d_in[11];
    const float* mha_fcb= (const float*)d_in[12];
    const float* mha_gw = (const float*)d_in[13];
    const float* mha_gb = (const float*)d_in[14];
    const float* w_ih   = (const float*)d_in[15];
    const float* w_hh   = (const float*)d_in[16];
    const float* b_ih   = (const float*)d_in[17];
    const float* b_hh   = (const float*)d_in[18];

    float* out   = (float*)d_out;
    const size_t N = (size_t)BSZ * NHID;
    float* out_hx   = out;
    float* out_cx   = out + N;
    float* out_mask = out + 2 * N;

    k1_input_attn<<<BSZ / K1_BPB, 256>>>(inp, hx, ia_wq, ia_wk, ia_wv, ia_fcw, ia_fcb, out_mask);

    dim3 g2(GATES / 128, BSZ / 128, NBO);
    k2_lstm_gemm<<<g2, 256>>>(hx, w_ih, w_hh, b_ih, b_hh);

    k3_lstm_ew<<<(unsigned)((N + 255) / 256), 256>>>(cx, out_cx);

    dim3 g4(NBO, BSZ / 64);
    k4_qkv<<<g4, 256>>>(mha_wq, mha_wk, mha_wv);

    k5_mha<<<BSZ, 256>>>(hx, mha_fcw, mha_fcb, mha_gw, mha_gb, out_hx);
}

// round 5
// speedup vs baseline: 1.8843x; 1.8843x over previous
#include <cuda_runtime.h>
#include <cuda_bf16.h>
#include <math.h>
#include <stdint.h>

#define BSZ   1024
#define NBIN  4
#define BSIN  128
#define NKEY  5
#define NBO   8
#define BSO   512
#define NHID  4096
#define DKQ   64
#define GATES 2048

// ------------- scratch (allocation-free: __device__ globals) -------------
__device__ float g_inp_use[(size_t)BSZ * NBO * BSO];
__device__ float g_gates  [(size_t)BSZ * NBO * GATES];
__device__ float g_hnew   [(size_t)BSZ * NBO * BSO];
__device__ float g_q2     [(size_t)BSZ * NBO * DKQ];
__device__ float g_k2     [(size_t)BSZ * NBO * DKQ];
__device__ float g_v2     [(size_t)BSZ * NBO * DKQ];
__device__ float g_mblk   [(size_t)BSZ * NBO];
// bf16 hi/lo split operands for the tensor-core LSTM GEMM
// A: [kb][m=1024][k=1024]  (k<512: inp_use, k>=512: hx)
__device__ __nv_bfloat16 g_ahi[(size_t)NBO * 1024 * 1024];
__device__ __nv_bfloat16 g_alo[(size_t)NBO * 1024 * 1024];
// B: [kb][n=2048][k=1024]  (k<512: w_ih^T, k>=512: w_hh^T)
__device__ __nv_bfloat16 g_bhi[(size_t)NBO * 2048 * 1024];
__device__ __nv_bfloat16 g_blo[(size_t)NBO * 2048 * 1024];

__device__ __forceinline__ float sigf(float x) { return 1.0f / (1.0f + expf(-x)); }

// ------------- f32x2 packed FMA helpers -------------
__device__ __forceinline__ unsigned long long pk2(float x, float y) {
    unsigned long long r;
    asm("mov.b64 %0, {%1, %2};" : "=l"(r) : "f"(x), "f"(y));
    return r;
}
__device__ __forceinline__ void fma2(unsigned long long& d, unsigned long long a, unsigned long long b) {
    asm("fma.rn.f32x2 %0, %1, %2, %0;" : "+l"(d) : "l"(a), "l"(b));
}
__device__ __forceinline__ float2 upk2(unsigned long long v) {
    float2 f;
    asm("mov.b64 {%0, %1}, %2;" : "=f"(f.x), "=f"(f.y) : "l"(v));
    return f;
}

// ------------- mma.sync / ldmatrix / cp.async helpers (sm_80 baseline PTX) ----
__device__ __forceinline__ uint32_t smem_u32(const void* p) {
    uint32_t a;
    asm("{ .reg .u64 t; cvta.to.shared.u64 t, %1; cvt.u32.u64 %0, t; }" : "=r"(a) : "l"(p));
    return a;
}
// swizzle for 64-byte rows: 16B slot ^= (row>>1)&3
__device__ __forceinline__ uint32_t swz64(uint32_t b) { return b ^ ((b >> 3) & 0x30); }

__device__ __forceinline__ void ldsm_x4(uint32_t addr, uint32_t* r) {
    asm volatile("ldmatrix.sync.aligned.m8n8.x4.shared.b16 {%0,%1,%2,%3}, [%4];"
                 : "=r"(r[0]), "=r"(r[1]), "=r"(r[2]), "=r"(r[3]) : "r"(addr));
}
__device__ __forceinline__ void mma_bf16(float* c, const uint32_t* a, uint32_t b0, uint32_t b1) {
    asm volatile("mma.sync.aligned.m16n8k16.row.col.f32.bf16.bf16.f32 "
                 "{%0,%1,%2,%3}, {%4,%5,%6,%7}, {%8,%9}, {%0,%1,%2,%3};"
                 : "+f"(c[0]), "+f"(c[1]), "+f"(c[2]), "+f"(c[3])
                 : "r"(a[0]), "r"(a[1]), "r"(a[2]), "r"(a[3]), "r"(b0), "r"(b1));
}
__device__ __forceinline__ void cpa16(uint32_t dst, const void* src) {
    asm volatile("cp.async.cg.shared.global [%0], [%1], 16;" :: "r"(dst), "l"(src));
}
__device__ __forceinline__ void cp_commit() { asm volatile("cp.async.commit_group;"); }
__device__ __forceinline__ void cp_wait1() { asm volatile("cp.async.wait_group 1;"); }
__device__ __forceinline__ void cp_wait0() { asm volatile("cp.async.wait_group 0;"); }

// =====================================================================
// K1: input attention + top-4 mask.  4 batch elements per CTA.
// =====================================================================
#define K1_BPB 4
__global__ void __launch_bounds__(256) k1_input_attn(
    const float* __restrict__ inp, const float* __restrict__ hx,
    const float* __restrict__ wq, const float* __restrict__ wk, const float* __restrict__ wv,
    const float* __restrict__ fcw, const float* __restrict__ fcb,
    float* __restrict__ mask_out)
{
    __shared__ float sx[K1_BPB][NKEY * BSIN];
    __shared__ float sk[K1_BPB][NKEY][DKQ];
    __shared__ float sv[K1_BPB][NKEY][DKQ];
    __shared__ float sq[K1_BPB][NBO][DKQ];
    __shared__ float so[K1_BPB][NBO][DKQ];
    __shared__ float sattn[K1_BPB][NBO][NKEY];
    __shared__ float smb[K1_BPB][NBO];

    const int tid = threadIdx.x;
    const int b0  = blockIdx.x * K1_BPB;

    for (int i = tid; i < K1_BPB * NKEY * BSIN; i += 256) {
        int bi = i / (NKEY * BSIN);
        int j  = i % (NKEY * BSIN);
        sx[bi][j] = (j < NBIN * BSIN) ? inp[(size_t)(b0 + bi) * (NBIN * BSIN) + j] : 0.0f;
    }
    __syncthreads();

    for (int g = tid; g < K1_BPB * NKEY * (DKQ / 4); g += 256) {
        int bi = g / (NKEY * 16);
        int r  = g % (NKEY * 16);
        int n  = r / 16;
        int e4 = (r % 16) * 4;
        const float* xp  = &sx[bi][n * BSIN];
        const float* wkp = wk + (size_t)(n * BSIN) * DKQ + e4;
        const float* wvp = wv + (size_t)(n * BSIN) * DKQ + e4;
        float4 ak = make_float4(0.f, 0.f, 0.f, 0.f);
        float4 av = make_float4(0.f, 0.f, 0.f, 0.f);
        for (int d = 0; d < BSIN; d++) {
            float xv  = xp[d];
            float4 a4 = *(const float4*)(wkp + (size_t)d * DKQ);
            float4 b4 = *(const float4*)(wvp + (size_t)d * DKQ);
            ak.x += xv * a4.x; ak.y += xv * a4.y; ak.z += xv * a4.z; ak.w += xv * a4.w;
            av.x += xv * b4.x; av.y += xv * b4.y; av.z += xv * b4.z; av.w += xv * b4.w;
        }
        *(float4*)&sk[bi][n][e4] = ak;
        *(float4*)&sv[bi][n][e4] = av;
    }

    for (int g = tid; g < K1_BPB * NBO * (DKQ / 4); g += 256) {
        int bi = g / (NBO * 16);
        int r  = g % (NBO * 16);
        int n  = r / 16;
        int e4 = (r % 16) * 4;
        const float* hp = hx + (size_t)(b0 + bi) * NHID + n * BSO;
        const float* wp = wq + (size_t)(n * BSO) * DKQ + e4;
        float4 a = make_float4(0.f, 0.f, 0.f, 0.f);
        for (int d = 0; d < BSO; d++) {
            float hv  = __ldg(hp + d);
            float4 w4 = *(const float4*)(wp + (size_t)d * DKQ);
            a.x += hv * w4.x; a.y += hv * w4.y; a.z += hv * w4.z; a.w += hv * w4.w;
        }
        *(float4*)&sq[bi][n][e4] = a;
    }
    __syncthreads();

    if (tid < K1_BPB * NBO) {
        int bi = tid / NBO, n = tid % NBO;
        float s[NKEY];
        float mx = -1e30f;
        for (int j = 0; j < NKEY; j++) {
            float a = 0.f;
            for (int e = 0; e < DKQ; e++) a += sq[bi][n][e] * sk[bi][j][e];
            a *= 0.125f;
            s[j] = a;
            mx = fmaxf(mx, a);
        }
        float den = 0.f;
        for (int j = 0; j < NKEY; j++) { s[j] = expf(s[j] - mx); den += s[j]; }
        float inv = 1.0f / den;
        for (int j = 0; j < NKEY; j++) sattn[bi][n][j] = s[j] * inv;
    }
    __syncthreads();

    if (tid < K1_BPB) {
        int bi = tid;
        float sc[NBO], t[NBO];
        for (int n = 0; n < NBO; n++) { sc[n] = sattn[bi][n][0]; t[n] = sc[n]; }
        for (int a = 0; a < 4; a++) {
            int mi = a;
            for (int b = a + 1; b < NBO; b++) if (t[b] > t[mi]) mi = b;
            float tmp = t[a]; t[a] = t[mi]; t[mi] = tmp;
        }
        float thr = t[3] - 0.01f;
        for (int n = 0; n < NBO; n++) {
            float m = (sc[n] > thr) ? 1.0f : 0.0f;
            smb[bi][n] = m;
            g_mblk[(size_t)(b0 + bi) * NBO + n] = m;
        }
    }
    __syncthreads();

    for (int i = tid; i < K1_BPB * NBO * DKQ; i += 256) {
        int bi = i / (NBO * DKQ);
        int r  = i % (NBO * DKQ);
        int n  = r / DKQ;
        int e  = r % DKQ;
        float a = 0.f;
        for (int j = 0; j < NKEY; j++) a += sattn[bi][n][j] * sv[bi][j][e];
        so[bi][n][e] = a;
    }
    __syncthreads();

    for (int g = tid; g < K1_BPB * NBO * (BSO / 4); g += 256) {
        int bi = g / (NBO * 128);
        int r  = g % (NBO * 128);
        int n  = r / 128;
        int c4 = (r % 128) * 4;
        float4 a = *(const float4*)&fcb[c4];
        const float* sp = so[bi][n];
        for (int e = 0; e < DKQ; e++) {
            float s   = sp[e];
            float4 w4 = *(const float4*)&fcw[(size_t)e * BSO + c4];
            a.x += s * w4.x; a.y += s * w4.y; a.z += s * w4.z; a.w += s * w4.w;
        }
        *(float4*)&g_inp_use[((size_t)(b0 + bi) * NBO + n) * BSO + c4] = a;
        float m = smb[bi][n];
        *(float4*)&mask_out[(size_t)(b0 + bi) * NHID + n * BSO + c4] = make_float4(m, m, m, m);
    }
}

// =====================================================================
// prep_b: transpose + bf16 hi/lo split of LSTM weights.
//   w[kb][k][n] (n contig) -> g_bhi/g_blo [kb][n][k] (k contig)
// =====================================================================
__global__ void __launch_bounds__(256) prep_b(
    const float* __restrict__ w_ih, const float* __restrict__ w_hh)
{
    __shared__ float ts[64][65];
    const int tid = threadIdx.x;
    const int n0  = blockIdx.x * 64;
    const int k0  = blockIdx.y * 64;
    const int kb  = blockIdx.z;

    const float* srcm = (k0 < 512) ? (w_ih + (size_t)kb * 512 * GATES)
                                   : (w_hh + (size_t)kb * 512 * GATES);
    const int krow0 = (k0 < 512) ? k0 : (k0 - 512);

#pragma unroll
    for (int p = 0; p < 16; p++) {
        int idx = p * 256 + tid;
        int r = idx >> 6;
        int c = idx & 63;
        ts[r][c] = srcm[(size_t)(krow0 + r) * GATES + n0 + c];
    }
    __syncthreads();

#pragma unroll
    for (int g = 0; g < 2; g++) {
        int n   = (tid >> 3) + g * 32;
        int kk0 = (tid & 7) * 8;
        union { __nv_bfloat16 h[8]; uint4 u; } vh, vl;
#pragma unroll
        for (int j = 0; j < 8; j++) {
            float x = ts[kk0 + j][n];
            __nv_bfloat16 hi = __float2bfloat16(x);
            vh.h[j] = hi;
            vl.h[j] = __float2bfloat16(x - __bfloat162float(hi));
        }
        size_t o = ((size_t)kb * GATES + n0 + n) * 1024 + k0 + kk0;
        *(uint4*)&g_bhi[o] = vh.u;
        *(uint4*)&g_blo[o] = vl.u;
    }
}

// =====================================================================
// prep_a: bf16 hi/lo split of activations -> g_ahi/g_alo [kb][m][k]
// =====================================================================
__global__ void __launch_bounds__(256) prep_a(const float* __restrict__ hx)
{
    size_t i8 = (size_t)blockIdx.x * 256 + threadIdx.x;
    size_t i  = i8 * 8;
    int k  = (int)(i & 1023);
    int m  = (int)((i >> 10) & 1023);
    int kb = (int)(i >> 20);

    const float* src = (k < 512)
        ? &g_inp_use[((size_t)m * NBO + kb) * BSO + k]
        : &hx[(size_t)m * NHID + kb * BSO + (k - 512)];

    float4 a = *(const float4*)src;
    float4 b = *(const float4*)(src + 4);
    float xs[8] = {a.x, a.y, a.z, a.w, b.x, b.y, b.z, b.w};
    union { __nv_bfloat16 h[8]; uint4 u; } vh, vl;
#pragma unroll
    for (int j = 0; j < 8; j++) {
        __nv_bfloat16 hi = __float2bfloat16(xs[j]);
        vh.h[j] = hi;
        vl.h[j] = __float2bfloat16(xs[j] - __bfloat162float(hi));
    }
    *(uint4*)&g_ahi[i] = vh.u;
    *(uint4*)&g_alo[i] = vl.u;
}

// =====================================================================
// K2M: LSTM gate GEMM on mma.sync bf16 (hi/lo split, 3 passes).
//   CTA tile 128x128, K-chunk 32, double-buffered cp.async.
//   8 warps = 2(m) x 4(n); warp tile 64x32.
//   B is [n][k] k-contiguous == col-major k x n: NON-trans ldmatrix,
//   fragment for n-subtile s of a 16n block = regs {r[s], r[s+2]}.
// =====================================================================
#define K2_STG   32768
#define K2_SMEM  (2 * K2_STG)
#define OFF_AH   0
#define OFF_AL   8192
#define OFF_BH   16384
#define OFF_BL   24576

__global__ void __launch_bounds__(256, 2) k2m_gemm()
{
    extern __shared__ char smem[];
    const int tid = threadIdx.x;
    const int wid = tid >> 5;
    const int lid = tid & 31;
    const uint32_t sbase = smem_u32(smem);
    const int nb = blockIdx.x * 128;
    const int mb = blockIdx.y * 128;
    const int kb = blockIdx.z;

    const __nv_bfloat16* Ah = g_ahi + ((size_t)kb * 1024 + mb) * 1024;
    const __nv_bfloat16* Al = g_alo + ((size_t)kb * 1024 + mb) * 1024;
    const __nv_bfloat16* Bh = g_bhi + ((size_t)kb * 2048 + nb) * 1024;
    const __nv_bfloat16* Bl = g_blo + ((size_t)kb * 2048 + nb) * 1024;

    const int mw = (wid >> 2) * 64;
    const int nw = (wid & 3) * 32;
    const int g  = lid >> 3;
    const int r  = lid & 7;

    // non-trans ldmatrix x4 address pattern (same for A and B):
    //   row = base + (g&1)*8 + r,  k-half = (g>>1)*8
    uint32_t offA[4][2], offB[2][2];
#pragma unroll
    for (int i = 0; i < 4; i++)
#pragma unroll
        for (int ks = 0; ks < 2; ks++) {
            int m = mw + i * 16 + (g & 1) * 8 + r;
            int k = ks * 16 + (g >> 1) * 8;
            offA[i][ks] = swz64((uint32_t)(m * 64 + k * 2));
        }
#pragma unroll
    for (int j = 0; j < 2; j++)
#pragma unroll
        for (int ks = 0; ks < 2; ks++) {
            int n = nw + j * 16 + (g & 1) * 8 + r;
            int k = ks * 16 + (g >> 1) * 8;
            offB[j][ks] = swz64((uint32_t)(n * 64 + k * 2));
        }

    float acc[4][4][4];
#pragma unroll
    for (int i = 0; i < 4; i++)
#pragma unroll
        for (int j = 0; j < 4; j++)
#pragma unroll
            for (int c = 0; c < 4; c++) acc[i][j][c] = 0.f;

    const int c_row0 = tid >> 2;
    const int c_sl   = tid & 3;

    // prologue: issue chunk 0
    {
        uint32_t sb = sbase;
#pragma unroll
        for (int p = 0; p < 2; p++) {
            int row = c_row0 + p * 64;
            uint32_t d = swz64((uint32_t)(row * 64 + c_sl * 16));
            size_t go = (size_t)row * 1024 + c_sl * 8;
            cpa16(sb + OFF_AH + d, Ah + go);
            cpa16(sb + OFF_AL + d, Al + go);
            cpa16(sb + OFF_BH + d, Bh + go);
            cpa16(sb + OFF_BL + d, Bl + go);
        }
        cp_commit();
    }

    for (int ch = 0; ch < 32; ch++) {
        if (ch + 1 < 32) {
            uint32_t sb = sbase + ((ch + 1) & 1) * K2_STG;
            int kc = (ch + 1) * 32;
#pragma unroll
            for (int p = 0; p < 2; p++) {
                int row = c_row0 + p * 64;
                uint32_t d = swz64((uint32_t)(row * 64 + c_sl * 16));
                size_t go = (size_t)row * 1024 + kc + c_sl * 8;
                cpa16(sb + OFF_AH + d, Ah + go);
                cpa16(sb + OFF_AL + d, Al + go);
                cpa16(sb + OFF_BH + d, Bh + go);
                cpa16(sb + OFF_BL + d, Bl + go);
            }
            cp_commit();
            cp_wait1();
        } else {
            cp_wait0();
        }
        __syncthreads();

        uint32_t sb = sbase + (ch & 1) * K2_STG;
#pragma unroll
        for (int ks = 0; ks < 2; ks++) {
            uint32_t bh[2][4], bl[2][4];
#pragma unroll
            for (int j = 0; j < 2; j++) {
                ldsm_x4(sb + OFF_BH + offB[j][ks], bh[j]);
                ldsm_x4(sb + OFF_BL + offB[j][ks], bl[j]);
            }
#pragma unroll
            for (int i = 0; i < 4; i++) {
                uint32_t ah[4], al[4];
                ldsm_x4(sb + OFF_AH + offA[i][ks], ah);
                ldsm_x4(sb + OFF_AL + offA[i][ks], al);
#pragma unroll
                for (int jn = 0; jn < 4; jn++) {
                    const int jj = jn >> 1;
                    const int ss = jn & 1;
                    mma_bf16(acc[i][jn], ah, bh[jj][ss], bh[jj][ss + 2]);
                    mma_bf16(acc[i][jn], ah, bl[jj][ss], bl[jj][ss + 2]);
                    mma_bf16(acc[i][jn], al, bh[jj][ss], bh[jj][ss + 2]);
                }
            }
        }
        __syncthreads();
    }

    // epilogue: write accumulators to g_gates
    const int rowc = lid >> 2;
    const int colc = (lid & 3) * 2;
#pragma unroll
    for (int i = 0; i < 4; i++) {
        int m0 = mb + mw + i * 16 + rowc;
#pragma unroll
        for (int jn = 0; jn < 4; jn++) {
            int n0 = nb + nw + jn * 8 + colc;
            *(float2*)&g_gates[((size_t)m0 * NBO + kb) * GATES + n0] =
                make_float2(acc[i][jn][0], acc[i][jn][1]);
            *(float2*)&g_gates[((size_t)(m0 + 8) * NBO + kb) * GATES + n0] =
                make_float2(acc[i][jn][2], acc[i][jn][3]);
        }
    }
}

// =====================================================================
// K3: LSTM elementwise (adds biases); writes h_new and cx_out.
// =====================================================================
__global__ void __launch_bounds__(256) k3_lstm_ew(
    const float* __restrict__ cx, const float* __restrict__ b_ih,
    const float* __restrict__ b_hh, float* __restrict__ cx_out)
{
    size_t i = (size_t)blockIdx.x * blockDim.x + threadIdx.x;
    if (i >= (size_t)BSZ * NBO * BSO) return;
    size_t bk = i / BSO;
    int kb = (int)(bk % NBO);
    int d  = (int)(i % BSO);
    const float* g  = &g_gates[bk * GATES];
    const float* bi = &b_ih[(size_t)kb * GATES];
    const float* bh = &b_hh[(size_t)kb * GATES];
    float ig = sigf(g[d]          + bi[d]          + bh[d]);
    float fg = sigf(g[d + 512]    + bi[d + 512]    + bh[d + 512]);
    float gg = tanhf(g[d + 1024]  + bi[d + 1024]   + bh[d + 1024]);
    float og = sigf(g[d + 1536]   + bi[d + 1536]   + bh[d + 1536]);
    float cb = cx[bk * BSO + d];
    float cn = fg * cb + ig * gg;
    float hn = og * tanhf(cn);
    g_hnew[i] = hn;
    float m = g_mblk[bk];
    cx_out[bk * BSO + d] = m * cn + (1.0f - m) * cb;
}

// =====================================================================
// K4: q2/k2/v2 GEMMs.  Tile 64x64, K=512, FFMA2.  grid (3,16,8).
// =====================================================================
__global__ void __launch_bounds__(256) k4_qkv(
    const float* __restrict__ wq, const float* __restrict__ wk, const float* __restrict__ wv)
{
    __shared__ float hs[64][33];
    __shared__ float ws[32][64];

    const int tid = threadIdx.x;
    const int mat = blockIdx.x;
    const int m0  = blockIdx.y * 64;
    const int kb  = blockIdx.z;
    const int tx  = tid & 15;
    const int ty  = tid >> 4;
    const int n4  = tx * 4;
    const int m4  = ty * 4;

    const float* w = ((mat == 0) ? wq : (mat == 1) ? wk : wv) + (size_t)kb * BSO * DKQ;

    unsigned long long acc[4][2];
#pragma unroll
    for (int j = 0; j < 4; j++) { acc[j][0] = 0ULL; acc[j][1] = 0ULL; }

    for (int kc = 0; kc < BSO; kc += 32) {
#pragma unroll
        for (int p = 0; p < 8; p++) {
            int idx = p * 256 + tid;
            int r  = idx >> 5;
            int kk = idx & 31;
            hs[r][kk] = g_hnew[((size_t)(m0 + r) * NBO + kb) * BSO + kc + kk];
        }
#pragma unroll
        for (int p = 0; p < 8; p++) {
            int idx = p * 256 + tid;
            int kk = idx >> 6;
            int n  = idx & 63;
            ws[kk][n] = w[(size_t)(kc + kk) * DKQ + n];
        }
        __syncthreads();

#pragma unroll 8
        for (int kk = 0; kk < 32; kk++) {
            unsigned long long b0 = *(const unsigned long long*)&ws[kk][n4];
            unsigned long long b1 = *(const unsigned long long*)&ws[kk][n4 + 2];
#pragma unroll
            for (int j = 0; j < 4; j++) {
                float a = hs[m4 + j][kk];
                unsigned long long aa = pk2(a, a);
                fma2(acc[j][0], aa, b0);
                fma2(acc[j][1], aa, b1);
            }
        }
        __syncthreads();
    }

    float* dst = (mat == 0) ? g_q2 : (mat == 1) ? g_k2 : g_v2;
#pragma unroll
    for (int j = 0; j < 4; j++) {
        float2 c0 = upk2(acc[j][0]);
        float2 c1 = upk2(acc[j][1]);
        float4 v = make_float4(c0.x, c0.y, c1.x, c1.y);
        *(float4*)&dst[((size_t)(m0 + m4 + j) * NBO + kb) * DKQ + n4] = v;
    }
}

// =====================================================================
// K5: MHA attend + fc/gate + final hx_out combine.  One CTA per batch.
// =====================================================================
__global__ void __launch_bounds__(256) k5_mha(
    const float* __restrict__ hx,
    const float* __restrict__ fcw, const float* __restrict__ fcb,
    const float* __restrict__ gw,  const float* __restrict__ gb,
    float* __restrict__ hx_out)
{
    __shared__ float sq2[NBO][DKQ];
    __shared__ float sk2[NBO][DKQ];
    __shared__ float sv2[NBO][DKQ];
    __shared__ float sat[NBO][NBO];
    __shared__ float so2[NBO][DKQ];

    const int tid = threadIdx.x;
    const size_t b = blockIdx.x;

    for (int i = tid; i < NBO * DKQ; i += 256) {
        ((float*)sq2)[i] = g_q2[b * NBO * DKQ + i];
        ((float*)sk2)[i] = g_k2[b * NBO * DKQ + i];
        ((float*)sv2)[i] = g_v2[b * NBO * DKQ + i];
    }
    __syncthreads();

    if (tid < 64) {
        int kq = tid >> 3, kj = tid & 7;
        float s = 0.f;
        for (int e = 0; e < DKQ; e++) s += sq2[kq][e] * sk2[kj][e];
        sat[kq][kj] = s * 0.125f;
    }
    __syncthreads();
    if (tid < NBO) {
        float mx = -1e30f;
        for (int j = 0; j < NBO; j++) mx = fmaxf(mx, sat[tid][j]);
        float den = 0.f;
        for (int j = 0; j < NBO; j++) { float e = expf(sat[tid][j] - mx); sat[tid][j] = e; den += e; }
        float inv = 1.0f / den;
        for (int j = 0; j < NBO; j++) sat[tid][j] *= inv;
    }
    __syncthreads();
    for (int i = tid; i < NBO * DKQ; i += 256) {
        int k = i >> 6, e = i & 63;
        float a = 0.f;
        for (int j = 0; j < NBO; j++) a += sat[k][j] * sv2[j][e];
        so2[k][e] = a;
    }
    __syncthreads();

    const int d0 = tid * 2;
    float2 ao[NBO], ag[NBO];
#pragma unroll
    for (int k = 0; k < NBO; k++) { ao[k] = make_float2(0.f, 0.f); ag[k] = make_float2(0.f, 0.f); }

    for (int e = 0; e < DKQ; e++) {
        float2 fw  = *(const float2*)&fcw[(size_t)e * BSO + d0];
        float2 gwv = *(const float2*)&gw[(size_t)e * BSO + d0];
#pragma unroll
        for (int k = 0; k < NBO; k++) {
            float o = so2[k][e];
            ao[k].x += o * fw.x;  ao[k].y += o * fw.y;
            ag[k].x += o * gwv.x; ag[k].y += o * gwv.y;
        }
    }

    float fb0 = fcb[d0], fb1 = fcb[d0 + 1];
    float gb0 = gb[d0],  gb1 = gb[d0 + 1];
#pragma unroll
    for (int k = 0; k < NBO; k++) {
        float m = g_mblk[b * NBO + k];
        float hn0 = g_hnew[(b * NBO + k) * BSO + d0];
        float hn1 = g_hnew[(b * NBO + k) * BSO + d0 + 1];
        float v0 = hn0 + sigf(ag[k].x + gb0) * tanhf(ao[k].x + fb0);
        float v1 = hn1 + sigf(ag[k].y + gb1) * tanhf(ao[k].y + fb1);
        size_t idx = b * NHID + (size_t)k * BSO + d0;
        hx_out[idx]     = m * v0 + (1.0f - m) * hx[idx];
        hx_out[idx + 1] = m * v1 + (1.0f - m) * hx[idx + 1];
    }
}

// =====================================================================
extern "C" void kernel_launch(void* const* d_in, const int* in_sizes, int n_in,
                              void* d_out, int out_size) {
    const float* inp    = (const float*)d_in[0];
    const float* hx     = (const float*)d_in[1];
    const float* cx     = (const float*)d_in[2];
    const float* ia_wq  = (const float*)d_in[3];
    const float* ia_wk  = (const float*)d_in[4];
    const float* ia_wv  = (const float*)d_in[5];
    const float* ia_fcw = (const float*)d_in[6];
    const float* ia_fcb = (const float*)d_in[7];
    const float* mha_wq = (const float*)d_in[8];
    const float* mha_wk = (const float*)d_in[9];
    const float* mha_wv = (const float*)d_in[10];
    const float* mha_fcw= (const float*)d_in[11];
    const float* mha_fcb= (const float*)d_in[12];
    const float* mha_gw = (const float*)d_in[13];
    const float* mha_gb = (const float*)d_in[14];
    const float* w_ih   = (const float*)d_in[15];
    const float* w_hh   = (const float*)d_in[16];
    const float* b_ih   = (const float*)d_in[17];
    const float* b_hh   = (const float*)d_in[18];

    float* out   = (float*)d_out;
    const size_t N = (size_t)BSZ * NHID;
    float* out_hx   = out;
    float* out_cx   = out + N;
    float* out_mask = out + 2 * N;

    cudaFuncSetAttribute(k2m_gemm, cudaFuncAttributeMaxDynamicSharedMemorySize, K2_SMEM);

    prep_b<<<dim3(GATES / 64, 1024 / 64, NBO), 256>>>(w_ih, w_hh);
    k1_input_attn<<<BSZ / K1_BPB, 256>>>(inp, hx, ia_wq, ia_wk, ia_wv, ia_fcw, ia_fcb, out_mask);
    prep_a<<<4096, 256>>>(hx);
    k2m_gemm<<<dim3(GATES / 128, BSZ / 128, NBO), 256, K2_SMEM>>>();
    k3_lstm_ew<<<(unsigned)((N + 255) / 256), 256>>>(cx, b_ih, b_hh, out_cx);
    k4_qkv<<<dim3(3, BSZ / 64, NBO), 256>>>(mha_wq, mha_wk, mha_wv);
    k5_mha<<<BSZ, 256>>>(hx, mha_fcw, mha_fcb, mha_gw, mha_gb, out_hx);
}

// round 6
// speedup vs baseline: 1.9971x; 1.0599x over previous
#include <cuda_runtime.h>
#include <cuda_bf16.h>
#include <math.h>
#include <stdint.h>

#define BSZ   1024
#define NBIN  4
#define BSIN  128
#define NKEY  5
#define NBO   8
#define BSO   512
#define NHID  4096
#define DKQ   64
#define GATES 2048

// ------------- scratch (allocation-free: __device__ globals) -------------
__device__ float g_gates  [(size_t)BSZ * NBO * GATES];
__device__ float g_hnew   [(size_t)BSZ * NBO * BSO];
__device__ float g_q2     [(size_t)BSZ * NBO * DKQ];
__device__ float g_k2     [(size_t)BSZ * NBO * DKQ];
__device__ float g_v2     [(size_t)BSZ * NBO * DKQ];
__device__ float g_mblk   [(size_t)BSZ * NBO];
// bf16 hi/lo split operands for the tensor-core LSTM GEMM
// A: [kb][m=1024][k=1024]  (k<512: inp_use, k>=512: hx)
__device__ __nv_bfloat16 g_ahi[(size_t)NBO * 1024 * 1024];
__device__ __nv_bfloat16 g_alo[(size_t)NBO * 1024 * 1024];
// B: [kb][n=2048][k=1024]  (k<512: w_ih^T, k>=512: w_hh^T)
__device__ __nv_bfloat16 g_bhi[(size_t)NBO * 2048 * 1024];
__device__ __nv_bfloat16 g_blo[(size_t)NBO * 2048 * 1024];

__device__ __forceinline__ float sigf(float x) { return 1.0f / (1.0f + expf(-x)); }

// ------------- f32x2 packed FMA helpers -------------
__device__ __forceinline__ unsigned long long pk2(float x, float y) {
    unsigned long long r;
    asm("mov.b64 %0, {%1, %2};" : "=l"(r) : "f"(x), "f"(y));
    return r;
}
__device__ __forceinline__ void fma2(unsigned long long& d, unsigned long long a, unsigned long long b) {
    asm("fma.rn.f32x2 %0, %1, %2, %0;" : "+l"(d) : "l"(a), "l"(b));
}
__device__ __forceinline__ float2 upk2(unsigned long long v) {
    float2 f;
    asm("mov.b64 {%0, %1}, %2;" : "=f"(f.x), "=f"(f.y) : "l"(v));
    return f;
}

// ------------- mma.sync / ldmatrix / cp.async helpers -------------
__device__ __forceinline__ uint32_t smem_u32(const void* p) {
    uint32_t a;
    asm("{ .reg .u64 t; cvta.to.shared.u64 t, %1; cvt.u32.u64 %0, t; }" : "=r"(a) : "l"(p));
    return a;
}
__device__ __forceinline__ uint32_t swz64(uint32_t b) { return b ^ ((b >> 3) & 0x30); }

__device__ __forceinline__ void ldsm_x4(uint32_t addr, uint32_t* r) {
    asm volatile("ldmatrix.sync.aligned.m8n8.x4.shared.b16 {%0,%1,%2,%3}, [%4];"
                 : "=r"(r[0]), "=r"(r[1]), "=r"(r[2]), "=r"(r[3]) : "r"(addr));
}
__device__ __forceinline__ void mma_bf16(float* c, const uint32_t* a, uint32_t b0, uint32_t b1) {
    asm volatile("mma.sync.aligned.m16n8k16.row.col.f32.bf16.bf16.f32 "
                 "{%0,%1,%2,%3}, {%4,%5,%6,%7}, {%8,%9}, {%0,%1,%2,%3};"
                 : "+f"(c[0]), "+f"(c[1]), "+f"(c[2]), "+f"(c[3])
                 : "r"(a[0]), "r"(a[1]), "r"(a[2]), "r"(a[3]), "r"(b0), "r"(b1));
}
__device__ __forceinline__ void cpa16(uint32_t dst, const void* src) {
    asm volatile("cp.async.cg.shared.global [%0], [%1], 16;" :: "r"(dst), "l"(src));
}
__device__ __forceinline__ void cp_commit() { asm volatile("cp.async.commit_group;"); }
__device__ __forceinline__ void cp_wait1() { asm volatile("cp.async.wait_group 1;"); }
__device__ __forceinline__ void cp_wait0() { asm volatile("cp.async.wait_group 0;"); }

// =====================================================================
// K1: input attention + top-4 mask + bf16 split of inp_use into A (k<512).
// =====================================================================
#define K1_BPB 4
__global__ void __launch_bounds__(256) k1_input_attn(
    const float* __restrict__ inp, const float* __restrict__ hx,
    const float* __restrict__ wq, const float* __restrict__ wk, const float* __restrict__ wv,
    const float* __restrict__ fcw, const float* __restrict__ fcb,
    float* __restrict__ mask_out)
{
    __shared__ float sx[K1_BPB][NKEY * BSIN];
    __shared__ float sk[K1_BPB][NKEY][DKQ];
    __shared__ float sv[K1_BPB][NKEY][DKQ];
    __shared__ float sq[K1_BPB][NBO][DKQ];
    __shared__ float so[K1_BPB][NBO][DKQ];
    __shared__ float sattn[K1_BPB][NBO][NKEY];
    __shared__ float smb[K1_BPB][NBO];

    const int tid = threadIdx.x;
    const int b0  = blockIdx.x * K1_BPB;

    for (int i = tid; i < K1_BPB * NKEY * BSIN; i += 256) {
        int bi = i / (NKEY * BSIN);
        int j  = i % (NKEY * BSIN);
        sx[bi][j] = (j < NBIN * BSIN) ? inp[(size_t)(b0 + bi) * (NBIN * BSIN) + j] : 0.0f;
    }
    __syncthreads();

    for (int g = tid; g < K1_BPB * NKEY * (DKQ / 4); g += 256) {
        int bi = g / (NKEY * 16);
        int r  = g % (NKEY * 16);
        int n  = r / 16;
        int e4 = (r % 16) * 4;
        const float* xp  = &sx[bi][n * BSIN];
        const float* wkp = wk + (size_t)(n * BSIN) * DKQ + e4;
        const float* wvp = wv + (size_t)(n * BSIN) * DKQ + e4;
        float4 ak = make_float4(0.f, 0.f, 0.f, 0.f);
        float4 av = make_float4(0.f, 0.f, 0.f, 0.f);
        for (int d = 0; d < BSIN; d++) {
            float xv  = xp[d];
            float4 a4 = *(const float4*)(wkp + (size_t)d * DKQ);
            float4 b4 = *(const float4*)(wvp + (size_t)d * DKQ);
            ak.x += xv * a4.x; ak.y += xv * a4.y; ak.z += xv * a4.z; ak.w += xv * a4.w;
            av.x += xv * b4.x; av.y += xv * b4.y; av.z += xv * b4.z; av.w += xv * b4.w;
        }
        *(float4*)&sk[bi][n][e4] = ak;
        *(float4*)&sv[bi][n][e4] = av;
    }

    for (int g = tid; g < K1_BPB * NBO * (DKQ / 4); g += 256) {
        int bi = g / (NBO * 16);
        int r  = g % (NBO * 16);
        int n  = r / 16;
        int e4 = (r % 16) * 4;
        const float* hp = hx + (size_t)(b0 + bi) * NHID + n * BSO;
        const float* wp = wq + (size_t)(n * BSO) * DKQ + e4;
        float4 a = make_float4(0.f, 0.f, 0.f, 0.f);
        for (int d = 0; d < BSO; d++) {
            float hv  = __ldg(hp + d);
            float4 w4 = *(const float4*)(wp + (size_t)d * DKQ);
            a.x += hv * w4.x; a.y += hv * w4.y; a.z += hv * w4.z; a.w += hv * w4.w;
        }
        *(float4*)&sq[bi][n][e4] = a;
    }
    __syncthreads();

    if (tid < K1_BPB * NBO) {
        int bi = tid / NBO, n = tid % NBO;
        float s[NKEY];
        float mx = -1e30f;
        for (int j = 0; j < NKEY; j++) {
            float a = 0.f;
            for (int e = 0; e < DKQ; e++) a += sq[bi][n][e] * sk[bi][j][e];
            a *= 0.125f;
            s[j] = a;
            mx = fmaxf(mx, a);
        }
        float den = 0.f;
        for (int j = 0; j < NKEY; j++) { s[j] = expf(s[j] - mx); den += s[j]; }
        float inv = 1.0f / den;
        for (int j = 0; j < NKEY; j++) sattn[bi][n][j] = s[j] * inv;
    }
    __syncthreads();

    if (tid < K1_BPB) {
        int bi = tid;
        float sc[NBO], t[NBO];
        for (int n = 0; n < NBO; n++) { sc[n] = sattn[bi][n][0]; t[n] = sc[n]; }
        for (int a = 0; a < 4; a++) {
            int mi = a;
            for (int b = a + 1; b < NBO; b++) if (t[b] > t[mi]) mi = b;
            float tmp = t[a]; t[a] = t[mi]; t[mi] = tmp;
        }
        float thr = t[3] - 0.01f;
        for (int n = 0; n < NBO; n++) {
            float m = (sc[n] > thr) ? 1.0f : 0.0f;
            smb[bi][n] = m;
            g_mblk[(size_t)(b0 + bi) * NBO + n] = m;
        }
    }
    __syncthreads();

    for (int i = tid; i < K1_BPB * NBO * DKQ; i += 256) {
        int bi = i / (NBO * DKQ);
        int r  = i % (NBO * DKQ);
        int n  = r / DKQ;
        int e  = r % DKQ;
        float a = 0.f;
        for (int j = 0; j < NKEY; j++) a += sattn[bi][n][j] * sv[bi][j][e];
        so[bi][n][e] = a;
    }
    __syncthreads();

    // inp_use = o @ fcw + fcb; write bf16 hi/lo split directly into A, plus mask
    for (int g = tid; g < K1_BPB * NBO * (BSO / 4); g += 256) {
        int bi = g / (NBO * 128);
        int r  = g % (NBO * 128);
        int n  = r / 128;
        int c4 = (r % 128) * 4;
        float4 a = *(const float4*)&fcb[c4];
        const float* sp = so[bi][n];
        for (int e = 0; e < DKQ; e++) {
            float s   = sp[e];
            float4 w4 = *(const float4*)&fcw[(size_t)e * BSO + c4];
            a.x += s * w4.x; a.y += s * w4.y; a.z += s * w4.z; a.w += s * w4.w;
        }
        float xs[4] = {a.x, a.y, a.z, a.w};
        union { __nv_bfloat16 h[4]; uint2 u; } vh, vl;
#pragma unroll
        for (int j = 0; j < 4; j++) {
            __nv_bfloat16 hi = __float2bfloat16(xs[j]);
            vh.h[j] = hi;
            vl.h[j] = __float2bfloat16(xs[j] - __bfloat162float(hi));
        }
        size_t ao = ((size_t)n * 1024 + (b0 + bi)) * 1024 + c4;
        *(uint2*)&g_ahi[ao] = vh.u;
        *(uint2*)&g_alo[ao] = vl.u;

        float m = smb[bi][n];
        *(float4*)&mask_out[(size_t)(b0 + bi) * NHID + n * BSO + c4] = make_float4(m, m, m, m);
    }
}

// =====================================================================
// prep_b: transpose + bf16 hi/lo split of LSTM weights.
// =====================================================================
__global__ void __launch_bounds__(256) prep_b(
    const float* __restrict__ w_ih, const float* __restrict__ w_hh)
{
    __shared__ float ts[64][65];
    const int tid = threadIdx.x;
    const int n0  = blockIdx.x * 64;
    const int k0  = blockIdx.y * 64;
    const int kb  = blockIdx.z;

    const float* srcm = (k0 < 512) ? (w_ih + (size_t)kb * 512 * GATES)
                                   : (w_hh + (size_t)kb * 512 * GATES);
    const int krow0 = (k0 < 512) ? k0 : (k0 - 512);

#pragma unroll
    for (int p = 0; p < 16; p++) {
        int idx = p * 256 + tid;
        int r = idx >> 6;
        int c = idx & 63;
        ts[r][c] = srcm[(size_t)(krow0 + r) * GATES + n0 + c];
    }
    __syncthreads();

#pragma unroll
    for (int g = 0; g < 2; g++) {
        int n   = (tid >> 3) + g * 32;
        int kk0 = (tid & 7) * 8;
        union { __nv_bfloat16 h[8]; uint4 u; } vh, vl;
#pragma unroll
        for (int j = 0; j < 8; j++) {
            float x = ts[kk0 + j][n];
            __nv_bfloat16 hi = __float2bfloat16(x);
            vh.h[j] = hi;
            vl.h[j] = __float2bfloat16(x - __bfloat162float(hi));
        }
        size_t o = ((size_t)kb * GATES + n0 + n) * 1024 + k0 + kk0;
        *(uint4*)&g_bhi[o] = vh.u;
        *(uint4*)&g_blo[o] = vl.u;
    }
}

// =====================================================================
// prep_a2: bf16 hi/lo split of hx -> g_ahi/g_alo (k >= 512 half)
// =====================================================================
__global__ void __launch_bounds__(256) prep_a2(const float* __restrict__ hx)
{
    size_t idx = (size_t)blockIdx.x * 256 + threadIdx.x;   // 524288 threads
    int k8 = (int)(idx & 63);
    int m  = (int)((idx >> 6) & 1023);
    int kb = (int)(idx >> 16);
    int k  = k8 * 8;

    const float* src = &hx[(size_t)m * NHID + kb * BSO + k];
    float4 a = *(const float4*)src;
    float4 b = *(const float4*)(src + 4);
    float xs[8] = {a.x, a.y, a.z, a.w, b.x, b.y, b.z, b.w};
    union { __nv_bfloat16 h[8]; uint4 u; } vh, vl;
#pragma unroll
    for (int j = 0; j < 8; j++) {
        __nv_bfloat16 hi = __float2bfloat16(xs[j]);
        vh.h[j] = hi;
        vl.h[j] = __float2bfloat16(xs[j] - __bfloat162float(hi));
    }
    size_t o = ((size_t)kb * 1024 + m) * 1024 + 512 + k;
    *(uint4*)&g_ahi[o] = vh.u;
    *(uint4*)&g_alo[o] = vl.u;
}

// =====================================================================
// K2M: LSTM gate GEMM on mma.sync bf16 (hi/lo split, 3 passes).
//   CTA tile 128x128, K-chunk 32, 3-stage cp.async pipeline,
//   ONE __syncthreads per chunk.
// =====================================================================
#define K2_STG   32768
#define K2_SMEM  (3 * K2_STG)          /* 98304 */
#define OFF_AH   0
#define OFF_AL   8192
#define OFF_BH   16384
#define OFF_BL   24576

__global__ void __launch_bounds__(256, 2) k2m_gemm()
{
    extern __shared__ char smem[];
    const int tid = threadIdx.x;
    const int wid = tid >> 5;
    const int lid = tid & 31;
    const uint32_t sbase = smem_u32(smem);
    const int nb = blockIdx.x * 128;
    const int mb = blockIdx.y * 128;
    const int kb = blockIdx.z;

    const __nv_bfloat16* Ah = g_ahi + ((size_t)kb * 1024 + mb) * 1024;
    const __nv_bfloat16* Al = g_alo + ((size_t)kb * 1024 + mb) * 1024;
    const __nv_bfloat16* Bh = g_bhi + ((size_t)kb * 2048 + nb) * 1024;
    const __nv_bfloat16* Bl = g_blo + ((size_t)kb * 2048 + nb) * 1024;

    const int mw = (wid >> 2) * 64;
    const int nw = (wid & 3) * 32;
    const int g  = lid >> 3;
    const int r  = lid & 7;

    uint32_t offA[4][2], offB[2][2];
#pragma unroll
    for (int i = 0; i < 4; i++)
#pragma unroll
        for (int ks = 0; ks < 2; ks++) {
            int m = mw + i * 16 + (g & 1) * 8 + r;
            int k = ks * 16 + (g >> 1) * 8;
            offA[i][ks] = swz64((uint32_t)(m * 64 + k * 2));
        }
#pragma unroll
    for (int j = 0; j < 2; j++)
#pragma unroll
        for (int ks = 0; ks < 2; ks++) {
            int n = nw + j * 16 + (g & 1) * 8 + r;
            int k = ks * 16 + (g >> 1) * 8;
            offB[j][ks] = swz64((uint32_t)(n * 64 + k * 2));
        }

    float acc[4][4][4];
#pragma unroll
    for (int i = 0; i < 4; i++)
#pragma unroll
        for (int j = 0; j < 4; j++)
#pragma unroll
            for (int c = 0; c < 4; c++) acc[i][j][c] = 0.f;

    const int c_row0 = tid >> 2;
    const int c_sl   = tid & 3;
    const uint32_t c_d0 = swz64((uint32_t)(c_row0 * 64 + c_sl * 16));
    const uint32_t c_d1 = swz64((uint32_t)((c_row0 + 64) * 64 + c_sl * 16));
    const size_t  c_g0 = (size_t)c_row0 * 1024 + c_sl * 8;
    const size_t  c_g1 = (size_t)(c_row0 + 64) * 1024 + c_sl * 8;

    // prologue: issue chunks 0 and 1
#pragma unroll
    for (int pc = 0; pc < 2; pc++) {
        uint32_t sb = sbase + pc * K2_STG;
        int kc = pc * 32;
        cpa16(sb + OFF_AH + c_d0, Ah + c_g0 + kc);
        cpa16(sb + OFF_AL + c_d0, Al + c_g0 + kc);
        cpa16(sb + OFF_BH + c_d0, Bh + c_g0 + kc);
        cpa16(sb + OFF_BL + c_d0, Bl + c_g0 + kc);
        cpa16(sb + OFF_AH + c_d1, Ah + c_g1 + kc);
        cpa16(sb + OFF_AL + c_d1, Al + c_g1 + kc);
        cpa16(sb + OFF_BH + c_d1, Bh + c_g1 + kc);
        cpa16(sb + OFF_BL + c_d1, Bl + c_g1 + kc);
        cp_commit();
    }

    int stage = 0;        // stage holding chunk ch
    int pstage = 2;       // stage to prefetch into
    for (int ch = 0; ch < 32; ch++) {
        if (ch + 1 < 32) cp_wait1(); else cp_wait0();
        __syncthreads();

        if (ch + 2 < 32) {
            uint32_t sb = sbase + pstage * K2_STG;
            int kc = (ch + 2) * 32;
            cpa16(sb + OFF_AH + c_d0, Ah + c_g0 + kc);
            cpa16(sb + OFF_AL + c_d0, Al + c_g0 + kc);
            cpa16(sb + OFF_BH + c_d0, Bh + c_g0 + kc);
            cpa16(sb + OFF_BL + c_d0, Bl + c_g0 + kc);
            cpa16(sb + OFF_AH + c_d1, Ah + c_g1 + kc);
            cpa16(sb + OFF_AL + c_d1, Al + c_g1 + kc);
            cpa16(sb + OFF_BH + c_d1, Bh + c_g1 + kc);
            cpa16(sb + OFF_BL + c_d1, Bl + c_g1 + kc);
            cp_commit();
        }

        uint32_t sb = sbase + stage * K2_STG;
#pragma unroll
        for (int ks = 0; ks < 2; ks++) {
            uint32_t bh[2][4], bl[2][4];
#pragma unroll
            for (int j = 0; j < 2; j++) {
                ldsm_x4(sb + OFF_BH + offB[j][ks], bh[j]);
                ldsm_x4(sb + OFF_BL + offB[j][ks], bl[j]);
            }
#pragma unroll
            for (int i = 0; i < 4; i++) {
                uint32_t ah[4], al[4];
                ldsm_x4(sb + OFF_AH + offA[i][ks], ah);
                ldsm_x4(sb + OFF_AL + offA[i][ks], al);
#pragma unroll
                for (int jn = 0; jn < 4; jn++) {
                    const int jj = jn >> 1;
                    const int ss = jn & 1;
                    mma_bf16(acc[i][jn], ah, bh[jj][ss], bh[jj][ss + 2]);
                    mma_bf16(acc[i][jn], ah, bl[jj][ss], bl[jj][ss + 2]);
                    mma_bf16(acc[i][jn], al, bh[jj][ss], bh[jj][ss + 2]);
                }
            }
        }
        stage  = (stage == 2) ? 0 : stage + 1;
        pstage = (pstage == 2) ? 0 : pstage + 1;
    }

    // epilogue
    const int rowc = lid >> 2;
    const int colc = (lid & 3) * 2;
#pragma unroll
    for (int i = 0; i < 4; i++) {
        int m0 = mb + mw + i * 16 + rowc;
#pragma unroll
        for (int jn = 0; jn < 4; jn++) {
            int n0 = nb + nw + jn * 8 + colc;
            *(float2*)&g_gates[((size_t)m0 * NBO + kb) * GATES + n0] =
                make_float2(acc[i][jn][0], acc[i][jn][1]);
            *(float2*)&g_gates[((size_t)(m0 + 8) * NBO + kb) * GATES + n0] =
                make_float2(acc[i][jn][2], acc[i][jn][3]);
        }
    }
}

// =====================================================================
// K3: LSTM elementwise (adds biases); writes h_new and cx_out.
// =====================================================================
__global__ void __launch_bounds__(256) k3_lstm_ew(
    const float* __restrict__ cx, const float* __restrict__ b_ih,
    const float* __restrict__ b_hh, float* __restrict__ cx_out)
{
    size_t i = (size_t)blockIdx.x * blockDim.x + threadIdx.x;
    if (i >= (size_t)BSZ * NBO * BSO) return;
    size_t bk = i / BSO;
    int kb = (int)(bk % NBO);
    int d  = (int)(i % BSO);
    const float* g  = &g_gates[bk * GATES];
    const float* bi = &b_ih[(size_t)kb * GATES];
    const float* bh = &b_hh[(size_t)kb * GATES];
    float ig = sigf(g[d]          + bi[d]          + bh[d]);
    float fg = sigf(g[d + 512]    + bi[d + 512]    + bh[d + 512]);
    float gg = tanhf(g[d + 1024]  + bi[d + 1024]   + bh[d + 1024]);
    float og = sigf(g[d + 1536]   + bi[d + 1536]   + bh[d + 1536]);
    float cb = cx[bk * BSO + d];
    float cn = fg * cb + ig * gg;
    float hn = og * tanhf(cn);
    g_hnew[i] = hn;
    float m = g_mblk[bk];
    cx_out[bk * BSO + d] = m * cn + (1.0f - m) * cb;
}

// =====================================================================
// K4: q2/k2/v2 GEMMs.  Tile 64x64, K=512, FFMA2.  grid (3,16,8).
// =====================================================================
__global__ void __launch_bounds__(256) k4_qkv(
    const float* __restrict__ wq, const float* __restrict__ wk, const float* __restrict__ wv)
{
    __shared__ float hs[64][33];
    __shared__ float ws[32][64];

    const int tid = threadIdx.x;
    const int mat = blockIdx.x;
    const int m0  = blockIdx.y * 64;
    const int kb  = blockIdx.z;
    const int tx  = tid & 15;
    const int ty  = tid >> 4;
    const int n4  = tx * 4;
    const int m4  = ty * 4;

    const float* w = ((mat == 0) ? wq : (mat == 1) ? wk : wv) + (size_t)kb * BSO * DKQ;

    unsigned long long acc[4][2];
#pragma unroll
    for (int j = 0; j < 4; j++) { acc[j][0] = 0ULL; acc[j][1] = 0ULL; }

    for (int kc = 0; kc < BSO; kc += 32) {
#pragma unroll
        for (int p = 0; p < 8; p++) {
            int idx = p * 256 + tid;
            int r  = idx >> 5;
            int kk = idx & 31;
            hs[r][kk] = g_hnew[((size_t)(m0 + r) * NBO + kb) * BSO + kc + kk];
        }
#pragma unroll
        for (int p = 0; p < 8; p++) {
            int idx = p * 256 + tid;
            int kk = idx >> 6;
            int n  = idx & 63;
            ws[kk][n] = w[(size_t)(kc + kk) * DKQ + n];
        }
        __syncthreads();

#pragma unroll 8
        for (int kk = 0; kk < 32; kk++) {
            unsigned long long b0 = *(const unsigned long long*)&ws[kk][n4];
            unsigned long long b1 = *(const unsigned long long*)&ws[kk][n4 + 2];
#pragma unroll
            for (int j = 0; j < 4; j++) {
                float a = hs[m4 + j][kk];
                unsigned long long aa = pk2(a, a);
                fma2(acc[j][0], aa, b0);
                fma2(acc[j][1], aa, b1);
            }
        }
        __syncthreads();
    }

    float* dst = (mat == 0) ? g_q2 : (mat == 1) ? g_k2 : g_v2;
#pragma unroll
    for (int j = 0; j < 4; j++) {
        float2 c0 = upk2(acc[j][0]);
        float2 c1 = upk2(acc[j][1]);
        float4 v = make_float4(c0.x, c0.y, c1.x, c1.y);
        *(float4*)&dst[((size_t)(m0 + m4 + j) * NBO + kb) * DKQ + n4] = v;
    }
}

// =====================================================================
// K5: MHA attend + fc/gate + final hx_out combine.  One CTA per batch.
// =====================================================================
__global__ void __launch_bounds__(256) k5_mha(
    const float* __restrict__ hx,
    const float* __restrict__ fcw, const float* __restrict__ fcb,
    const float* __restrict__ gw,  const float* __restrict__ gb,
    float* __restrict__ hx_out)
{
    __shared__ float sq2[NBO][DKQ];
    __shared__ float sk2[NBO][DKQ];
    __shared__ float sv2[NBO][DKQ];
    __shared__ float sat[NBO][NBO];
    __shared__ float so2[NBO][DKQ];

    const int tid = threadIdx.x;
    const size_t b = blockIdx.x;

    for (int i = tid; i < NBO * DKQ; i += 256) {
        ((float*)sq2)[i] = g_q2[b * NBO * DKQ + i];
        ((float*)sk2)[i] = g_k2[b * NBO * DKQ + i];
        ((float*)sv2)[i] = g_v2[b * NBO * DKQ + i];
    }
    __syncthreads();

    if (tid < 64) {
        int kq = tid >> 3, kj = tid & 7;
        float s = 0.f;
        for (int e = 0; e < DKQ; e++) s += sq2[kq][e] * sk2[kj][e];
        sat[kq][kj] = s * 0.125f;
    }
    __syncthreads();
    if (tid < NBO) {
        float mx = -1e30f;
        for (int j = 0; j < NBO; j++) mx = fmaxf(mx, sat[tid][j]);
        float den = 0.f;
        for (int j = 0; j < NBO; j++) { float e = expf(sat[tid][j] - mx); sat[tid][j] = e; den += e; }
        float inv = 1.0f / den;
        for (int j = 0; j < NBO; j++) sat[tid][j] *= inv;
    }
    __syncthreads();
    for (int i = tid; i < NBO * DKQ; i += 256) {
        int k = i >> 6, e = i & 63;
        float a = 0.f;
        for (int j = 0; j < NBO; j++) a += sat[k][j] * sv2[j][e];
        so2[k][e] = a;
    }
    __syncthreads();

    const int d0 = tid * 2;
    float2 ao[NBO], ag[NBO];
#pragma unroll
    for (int k = 0; k < NBO; k++) { ao[k] = make_float2(0.f, 0.f); ag[k] = make_float2(0.f, 0.f); }

    for (int e = 0; e < DKQ; e++) {
        float2 fw  = *(const float2*)&fcw[(size_t)e * BSO + d0];
        float2 gwv = *(const float2*)&gw[(size_t)e * BSO + d0];
#pragma unroll
        for (int k = 0; k < NBO; k++) {
            float o = so2[k][e];
            ao[k].x += o * fw.x;  ao[k].y += o * fw.y;
            ag[k].x += o * gwv.x; ag[k].y += o * gwv.y;
        }
    }

    float fb0 = fcb[d0], fb1 = fcb[d0 + 1];
    float gb0 = gb[d0],  gb1 = gb[d0 + 1];
#pragma unroll
    for (int k = 0; k < NBO; k++) {
        float m = g_mblk[b * NBO + k];
        float hn0 = g_hnew[(b * NBO + k) * BSO + d0];
        float hn1 = g_hnew[(b * NBO + k) * BSO + d0 + 1];
        float v0 = hn0 + sigf(ag[k].x + gb0) * tanhf(ao[k].x + fb0);
        float v1 = hn1 + sigf(ag[k].y + gb1) * tanhf(ao[k].y + fb1);
        size_t idx = b * NHID + (size_t)k * BSO + d0;
        hx_out[idx]     = m * v0 + (1.0f - m) * hx[idx];
        hx_out[idx + 1] = m * v1 + (1.0f - m) * hx[idx + 1];
    }
}

// =====================================================================
extern "C" void kernel_launch(void* const* d_in, const int* in_sizes, int n_in,
                              void* d_out, int out_size) {
    const float* inp    = (const float*)d_in[0];
    const float* hx     = (const float*)d_in[1];
    const float* cx     = (const float*)d_in[2];
    const float* ia_wq  = (const float*)d_in[3];
    const float* ia_wk  = (const float*)d_in[4];
    const float* ia_wv  = (const float*)d_in[5];
    const float* ia_fcw = (const float*)d_in[6];
    const float* ia_fcb = (const float*)d_in[7];
    const float* mha_wq = (const float*)d_in[8];
    const float* mha_wk = (const float*)d_in[9];
    const float* mha_wv = (const float*)d_in[10];
    const float* mha_fcw= (const float*)d_in[11];
    const float* mha_fcb= (const float*)d_in[12];
    const float* mha_gw = (const float*)d_in[13];
    const float* mha_gb = (const float*)d_in[14];
    const float* w_ih   = (const float*)d_in[15];
    const float* w_hh   = (const float*)d_in[16];
    const float* b_ih   = (const float*)d_in[17];
    const float* b_hh   = (const float*)d_in[18];

    float* out   = (float*)d_out;
    const size_t N = (size_t)BSZ * NHID;
    float* out_hx   = out;
    float* out_cx   = out + N;
    float* out_mask = out + 2 * N;

    cudaFuncSetAttribute(k2m_gemm, cudaFuncAttributeMaxDynamicSharedMemorySize, K2_SMEM);

    prep_b<<<dim3(GATES / 64, 1024 / 64, NBO), 256>>>(w_ih, w_hh);
    prep_a2<<<2048, 256>>>(hx);
    k1_input_attn<<<BSZ / K1_BPB, 256>>>(inp, hx, ia_wq, ia_wk, ia_wv, ia_fcw, ia_fcb, out_mask);
    k2m_gemm<<<dim3(GATES / 128, BSZ / 128, NBO), 256, K2_SMEM>>>();
    k3_lstm_ew<<<(unsigned)((N + 255) / 256), 256>>>(cx, b_ih, b_hh, out_cx);
    k4_qkv<<<dim3(3, BSZ / 64, NBO), 256>>>(mha_wq, mha_wk, mha_wv);
    k5_mha<<<BSZ, 256>>>(hx, mha_fcw, mha_fcb, mha_gw, mha_gb, out_hx);
}